// round 5
// baseline (speedup 1.0000x reference)
#include <cuda_runtime.h>
#include <cuda_fp16.h>
#include <cuda_bf16.h>
#include <math.h>
#include <stdint.h>

#define BATCH   8
#define NN      64
#define KTOT    65536
#define SPLITS  64
#define KCH     (KTOT / SPLITS)   // 1024
#define TILE_K  32
#define NTILES  (KCH / TILE_K)    // 32
#define STAGES  4
#define HSTRIDE 40                // fp16 smem row stride (80B)
#define ITERS   10

__device__ float g_gram[BATCH * NN * NN];

__global__ void zero_gram_kernel() {
    int idx = blockIdx.x * blockDim.x + threadIdx.x;
    if (idx < BATCH * NN * NN) g_gram[idx] = 0.0f;
}

__device__ __forceinline__ uint32_t smem_u32(const void* p) {
    return (uint32_t)__cvta_generic_to_shared(p);
}

// ---------------------------------------------------------------------------
// Kernel 1: split-K symmetric Gram, upper-triangle-only fp16 mma m16n8k16.
// grid = (SPLITS, BATCH), block = 320 (10 warps).
// Warp w computes 2 adjacent 16x8 tiles: rows [16*wr, +16), cols [wc, wc+16).
// Tile map covers exactly the 20 upper-tri tiles of the 4x8 tile grid.
// cp.async 4-stage fp32 staging -> fp16 convert -> mma; 1 sync per tile.
// ---------------------------------------------------------------------------
__global__ void __launch_bounds__(320) gram_mma_kernel(const float* __restrict__ feats) {
    __shared__ __align__(16) float  fstage[STAGES][64 * TILE_K];   // 32 KB
    __shared__ __align__(16) __half hbuf[2][64 * HSTRIDE];         // 10 KB

    const int tid  = threadIdx.x;
    const int wid  = tid >> 5;       // 0..9
    const int lane = tid & 31;
    const int tg   = lane & 3;

    const int b = blockIdx.y;
    const int s = blockIdx.x;
    const float* base = feats + (size_t)b * NN * KTOT + (size_t)s * KCH;

    // warp -> (row block r, col base cb) map; 20 upper-tri 16x8 tiles, 2/warp
    // wr  = {0,0,0,0,1,1,1,2,2,3}
    // wc16= {0,1,2,3,1,2,3,2,3,3}  (col base = wc16*16)
    const uint64_t WRP = 0x3221110000ULL;
    const uint64_t WCP = 0x3323213210ULL;
    const int r  = (int)((WRP >> (wid * 4)) & 0xF);
    const int cb = (int)((WCP >> (wid * 4)) & 0xF) * 16;

    // ldmatrix addressing (same fragment scheme as validated R4 kernel)
    const int a_row  = 16 * r + (lane & 7) + ((lane >> 3) & 1) * 8;
    const int a_koff = (lane >> 4) * 8;
    const int b_col  = cb + (lane & 7) + ((lane >> 4) & 1) * 8;
    const int b_koff = ((lane >> 3) & 1) * 8;

    // fill roles: threads 0..255 move data (2 float4 chunks per tile each)
    const bool filler = (tid < 256);
    const int c0row = tid >> 3,        c0c4 = tid & 7;
    const int c1row = (tid >> 3) + 32, c1c4 = tid & 7;

    float acc[2][4];
#pragma unroll
    for (int i = 0; i < 2; ++i)
#pragma unroll
        for (int j = 0; j < 4; ++j) acc[i][j] = 0.0f;

#define CP16(dst, src) \
    asm volatile("cp.async.ca.shared.global [%0], [%1], 16;" :: "r"(dst), "l"(src))
#define CP_COMMIT() asm volatile("cp.async.commit_group;" ::: "memory")

    // prologue: issue tiles 0..2
    if (filler) {
#pragma unroll
        for (int p = 0; p < 3; ++p) {
            const float* g = base + p * TILE_K;
            CP16(smem_u32(&fstage[p][c0row * TILE_K + c0c4 * 4]),
                 g + (size_t)c0row * KTOT + c0c4 * 4);
            CP16(smem_u32(&fstage[p][c1row * TILE_K + c1c4 * 4]),
                 g + (size_t)c1row * KTOT + c1c4 * 4);
            CP_COMMIT();
        }
    }

    for (int t = 0; t < NTILES; ++t) {
        if (filler) {
            if (t + 3 < NTILES) {
                const int st = (t + 3) & 3;
                const float* g = base + (t + 3) * TILE_K;
                CP16(smem_u32(&fstage[st][c0row * TILE_K + c0c4 * 4]),
                     g + (size_t)c0row * KTOT + c0c4 * 4);
                CP16(smem_u32(&fstage[st][c1row * TILE_K + c1c4 * 4]),
                     g + (size_t)c1row * KTOT + c1c4 * 4);
                CP_COMMIT();
                asm volatile("cp.async.wait_group 3;" ::: "memory");
            } else {
                asm volatile("cp.async.wait_group 0;" ::: "memory");
            }
            // convert fp32 stage -> fp16 buf (each thread touches only its own chunks)
            const int st = t & 3;
            float4 v0 = *reinterpret_cast<const float4*>(&fstage[st][c0row * TILE_K + c0c4 * 4]);
            float4 v1 = *reinterpret_cast<const float4*>(&fstage[st][c1row * TILE_K + c1c4 * 4]);
            __half* H = &hbuf[t & 1][0];
            *reinterpret_cast<__half2*>(&H[c0row * HSTRIDE + c0c4 * 4])     = __float22half2_rn(make_float2(v0.x, v0.y));
            *reinterpret_cast<__half2*>(&H[c0row * HSTRIDE + c0c4 * 4 + 2]) = __float22half2_rn(make_float2(v0.z, v0.w));
            *reinterpret_cast<__half2*>(&H[c1row * HSTRIDE + c1c4 * 4])     = __float22half2_rn(make_float2(v1.x, v1.y));
            *reinterpret_cast<__half2*>(&H[c1row * HSTRIDE + c1c4 * 4 + 2]) = __float22half2_rn(make_float2(v1.z, v1.w));
        }
        __syncthreads();

        const __half* S = &hbuf[t & 1][0];
#pragma unroll
        for (int kk = 0; kk < 2; ++kk) {
            const int k0 = kk * 16;
            uint32_t a0, a1, a2, a3, b01[2], b23[2];
            {
                uint32_t addr = smem_u32(S + a_row * HSTRIDE + k0 + a_koff);
                asm volatile("ldmatrix.sync.aligned.m8n8.x4.shared.b16 {%0,%1,%2,%3}, [%4];"
                             : "=r"(a0), "=r"(a1), "=r"(a2), "=r"(a3) : "r"(addr));
            }
            {
                uint32_t addr = smem_u32(S + b_col * HSTRIDE + k0 + b_koff);
                asm volatile("ldmatrix.sync.aligned.m8n8.x4.shared.b16 {%0,%1,%2,%3}, [%4];"
                             : "=r"(b01[0]), "=r"(b01[1]), "=r"(b23[0]), "=r"(b23[1]) : "r"(addr));
            }
#define MMA16(accv, bb)                                                         \
    asm volatile("mma.sync.aligned.m16n8k16.row.col.f32.f16.f16.f32 "          \
                 "{%0,%1,%2,%3}, {%4,%5,%6,%7}, {%8,%9}, {%0,%1,%2,%3};"       \
                 : "+f"(accv[0]), "+f"(accv[1]), "+f"(accv[2]), "+f"(accv[3])  \
                 : "r"(a0), "r"(a1), "r"(a2), "r"(a3), "r"(bb[0]), "r"(bb[1]))
            MMA16(acc[0], b01);
            MMA16(acc[1], b23);
#undef MMA16
        }
    }
#undef CP16
#undef CP_COMMIT

    // epilogue: direct writes for computed tiles; mirror off-diagonal tiles to [j,i]
    float* gb = g_gram + (size_t)b * NN * NN;
    const int r0 = 16 * r + (lane >> 2);
#pragma unroll
    for (int nt = 0; nt < 2; ++nt) {
        const int col   = cb + nt * 8 + tg * 2;
        const int ctile = (cb >> 3) + nt;
        const bool diag = ((ctile >> 1) == r);
        atomicAdd(&gb[(r0)     * NN + col    ], acc[nt][0]);
        atomicAdd(&gb[(r0)     * NN + col + 1], acc[nt][1]);
        atomicAdd(&gb[(r0 + 8) * NN + col    ], acc[nt][2]);
        atomicAdd(&gb[(r0 + 8) * NN + col + 1], acc[nt][3]);
        if (!diag) {
            atomicAdd(&gb[(col)     * NN + r0    ], acc[nt][0]);
            atomicAdd(&gb[(col + 1) * NN + r0    ], acc[nt][1]);
            atomicAdd(&gb[(col)     * NN + r0 + 8], acc[nt][2]);
            atomicAdd(&gb[(col + 1) * NN + r0 + 8], acc[nt][3]);
        }
    }
}

// ---------------------------------------------------------------------------
// Kernel 2: CRF iterations + output (vector-state reduction, unchanged)
// ---------------------------------------------------------------------------
__global__ void crf_kernel(const float* __restrict__ logits,
                           const float* __restrict__ W,
                           float* __restrict__ out) {
    const int b = blockIdx.x;
    const int i = threadIdx.x;   // 0..63

    __shared__ float pp[64][65];
    __shared__ float e[64];
    __shared__ float nrm[64];
    __shared__ float lg[64];
    __shared__ float red[64];

    const float* gb = g_gram + b * NN * NN;

    nrm[i] = sqrtf(gb[i * NN + i]);
    lg[i]  = logits[b * NN + i];
    __syncthreads();

    const float ni = nrm[i];
#pragma unroll 4
    for (int j = 0; j < NN; ++j) {
        const float dot  = gb[i * NN + j];
        const float sim  = dot / (ni * nrm[j] + 1e-6f);
        const float wsym = 0.5f * (W[i * NN + j] + W[j * NN + i]);
        pp[i][j] = sim * wsym;
    }
    e[i] = 0.0f;
    __syncthreads();

    const float li = lg[i];
    for (int it = 0; it < ITERS; ++it) {
        float acc = 0.0f;
#pragma unroll 8
        for (int j = 0; j < NN; ++j) {
            const float p = 1.0f / (1.0f + expf(-(li + e[j])));
            acc += (2.0f * p - 1.0f) * pp[i][j];
        }
        __syncthreads();
        e[i] = acc;
        __syncthreads();
    }

    red[i] = e[i];
    __syncthreads();
    for (int s = 32; s > 0; s >>= 1) {
        if (i < s) red[i] += red[i + s];
        __syncthreads();
    }
    const float meanE = red[0] * (1.0f / 64.0f);
    out[b * NN + i] = lg[i] + meanE;
}

extern "C" void kernel_launch(void* const* d_in, const int* in_sizes, int n_in,
                              void* d_out, int out_size) {
    const float* a_inter = (const float*)d_in[0];  // [8,64,64,32,32]
    const float* logits  = (const float*)d_in[1];  // [8,64]
    const float* W       = (const float*)d_in[2];  // [1,64,64]
    float* out           = (float*)d_out;          // [8,64]

    zero_gram_kernel<<<(BATCH * NN * NN + 255) / 256, 256>>>();

    dim3 grid(SPLITS, BATCH);
    gram_mma_kernel<<<grid, 320>>>(a_inter);

    crf_kernel<<<BATCH, 64>>>(logits, W, out);
}

// round 6
// speedup vs baseline: 1.0279x; 1.0279x over previous
#include <cuda_runtime.h>
#include <cuda_fp16.h>
#include <cuda_bf16.h>
#include <math.h>
#include <stdint.h>

#define BATCH   8
#define NN      64
#define KTOT    65536
#define SPLITS  32
#define KCH     (KTOT / SPLITS)   // 2048
#define TILE_K  128               // floats per row per tile (512B bursts)
#define NTILES  (KCH / TILE_K)    // 16
#define HSTRIDE 136               // fp16 smem row stride (272B): 4r mod 32 banks, conflict-free ldmatrix
#define ITERS   10

// Gram scratch [B][N][N]; zero-initialized at module load, re-zeroed by crf_kernel
__device__ float g_gram[BATCH * NN * NN];

__device__ __forceinline__ uint32_t smem_u32(const void* p) {
    return (uint32_t)__cvta_generic_to_shared(p);
}

// ---------------------------------------------------------------------------
// Kernel 1: split-K Gram via fp16 mma.sync m16n8k16 + ldmatrix.
// grid = (SPLITS, BATCH), block = 256 (8 warps: 4(M) x 2(N)).
// Each CTA: C[64,64] partial over K=2048, in 16 tiles of K=128.
// DRAM: each warp-instruction reads 512B contiguous from one row (page-friendly).
// Double-buffered fp16 smem tile; 1 __syncthreads per tile.
// ---------------------------------------------------------------------------
__global__ void __launch_bounds__(256) gram_mma_kernel(const float* __restrict__ feats) {
    __shared__ __align__(16) __half hbuf[2][64 * HSTRIDE];   // 2 x 17 KB

    const int tid  = threadIdx.x;
    const int wid  = tid >> 5;
    const int lane = tid & 31;
    const int tg   = lane & 3;
    const int wm   = wid >> 1;       // 0..3 -> C rows [wm*16, +16)
    const int wn   = wid & 1;        // 0..1 -> C cols [wn*32, +32)

    const int b = blockIdx.y;
    const int s = blockIdx.x;
    const float* base = feats + (size_t)b * NN * KTOT + (size_t)s * KCH;

    // fill mapping: warp w reads rows {w, w+8, ..., w+56}; lane covers 16B chunk
    // -> each LDG.128 warp-instruction = 512B contiguous from ONE row.
    const int r0   = tid >> 5;        // == wid
    const int coff = (tid & 31) * 4;  // float offset within the 128-float tile row

    // ldmatrix fragment addressing (validated R4 scheme, HSTRIDE updated)
    const int a_row  = wm * 16 + (lane & 7) + ((lane >> 3) & 1) * 8;
    const int a_koff = (lane >> 4) * 8;
    const int b_col  = wn * 32 + (lane & 7) + ((lane >> 4) & 1) * 8;
    const int b_koff = ((lane >> 3) & 1) * 8;

    float c[4][4];
#pragma unroll
    for (int i = 0; i < 4; ++i)
#pragma unroll
        for (int j = 0; j < 4; ++j) c[i][j] = 0.0f;

#define STORE8(buf, row, off, v)                                                     \
    do {                                                                             \
        *reinterpret_cast<__half2*>(&hbuf[buf][(row) * HSTRIDE + (off)])     =       \
            __float22half2_rn(make_float2((v).x, (v).y));                            \
        *reinterpret_cast<__half2*>(&hbuf[buf][(row) * HSTRIDE + (off) + 2]) =       \
            __float22half2_rn(make_float2((v).z, (v).w));                            \
    } while (0)

    // prologue: load tile 0 into registers, store to buf 0
    {
        float4 p[8];
#pragma unroll
        for (int i = 0; i < 8; ++i)
            p[i] = *reinterpret_cast<const float4*>(base + (size_t)(r0 + 8 * i) * KTOT + coff);
#pragma unroll
        for (int i = 0; i < 8; ++i)
            STORE8(0, r0 + 8 * i, coff, p[i]);
    }

    for (int t = 0; t < NTILES; ++t) {
        __syncthreads();   // buf[t&1] ready; all warps done with buf[(t+1)&1]

        // prefetch tile t+1 into registers (8 independent LDG.128, 512B bursts)
        float4 p[8];
        if (t + 1 < NTILES) {
            const float* nxt = base + (t + 1) * TILE_K;
#pragma unroll
            for (int i = 0; i < 8; ++i)
                p[i] = *reinterpret_cast<const float4*>(nxt + (size_t)(r0 + 8 * i) * KTOT + coff);
        }

        // mainloop: 8 k-steps of 16 over buf[t&1]
        const __half* S = &hbuf[t & 1][0];
#pragma unroll
        for (int kk = 0; kk < 8; ++kk) {
            const int k0 = kk * 16;
            uint32_t a0, a1, a2, a3, b01[2], b23[2], b45[2], b67[2];
            {
                uint32_t addr = smem_u32(S + a_row * HSTRIDE + k0 + a_koff);
                asm volatile("ldmatrix.sync.aligned.m8n8.x4.shared.b16 {%0,%1,%2,%3}, [%4];"
                             : "=r"(a0), "=r"(a1), "=r"(a2), "=r"(a3) : "r"(addr));
            }
            {
                uint32_t addr = smem_u32(S + b_col * HSTRIDE + k0 + b_koff);
                asm volatile("ldmatrix.sync.aligned.m8n8.x4.shared.b16 {%0,%1,%2,%3}, [%4];"
                             : "=r"(b01[0]), "=r"(b01[1]), "=r"(b23[0]), "=r"(b23[1]) : "r"(addr));
            }
            {
                uint32_t addr = smem_u32(S + (b_col + 16) * HSTRIDE + k0 + b_koff);
                asm volatile("ldmatrix.sync.aligned.m8n8.x4.shared.b16 {%0,%1,%2,%3}, [%4];"
                             : "=r"(b45[0]), "=r"(b45[1]), "=r"(b67[0]), "=r"(b67[1]) : "r"(addr));
            }
#define MMA16(accv, bb)                                                         \
    asm volatile("mma.sync.aligned.m16n8k16.row.col.f32.f16.f16.f32 "          \
                 "{%0,%1,%2,%3}, {%4,%5,%6,%7}, {%8,%9}, {%0,%1,%2,%3};"       \
                 : "+f"(accv[0]), "+f"(accv[1]), "+f"(accv[2]), "+f"(accv[3])  \
                 : "r"(a0), "r"(a1), "r"(a2), "r"(a3), "r"(bb[0]), "r"(bb[1]))
            MMA16(c[0], b01);
            MMA16(c[1], b23);
            MMA16(c[2], b45);
            MMA16(c[3], b67);
#undef MMA16
        }

        // store prefetched tile into the other buffer
        if (t + 1 < NTILES) {
            const int nbuf = (t + 1) & 1;
#pragma unroll
            for (int i = 0; i < 8; ++i)
                STORE8(nbuf, r0 + 8 * i, coff, p[i]);
        }
    }
#undef STORE8

    // epilogue: atomic-accumulate partial C into g_gram[b]
    float* gb = g_gram + (size_t)b * NN * NN;
    const int re = wm * 16 + (lane >> 2);
#pragma unroll
    for (int nt = 0; nt < 4; ++nt) {
        const int col = wn * 32 + nt * 8 + tg * 2;
        atomicAdd(&gb[(re)     * NN + col    ], c[nt][0]);
        atomicAdd(&gb[(re)     * NN + col + 1], c[nt][1]);
        atomicAdd(&gb[(re + 8) * NN + col    ], c[nt][2]);
        atomicAdd(&gb[(re + 8) * NN + col + 1], c[nt][3]);
    }
}

// ---------------------------------------------------------------------------
// Kernel 2: CRF iterations + output; also re-zeroes g_gram for the next call.
// State reduction: l[b,i,j] = logits[b,j] + e[i]; only e (len 64) evolves:
//   e'[i] = sum_j (2*sigmoid(logits[i] + e[j]) - 1) * pp[i,j],  e0 = 0
//   out[b,j] = logits[b,j] + mean_i(e[i])
// ---------------------------------------------------------------------------
__global__ void crf_kernel(const float* __restrict__ logits,
                           const float* __restrict__ W,
                           float* __restrict__ out) {
    const int b = blockIdx.x;
    const int i = threadIdx.x;   // 0..63

    __shared__ float pp[64][65];
    __shared__ float e[64];
    __shared__ float nrm[64];
    __shared__ float lg[64];
    __shared__ float red[64];

    float* gb = g_gram + b * NN * NN;

    nrm[i] = sqrtf(gb[i * NN + i]);
    lg[i]  = logits[b * NN + i];
    __syncthreads();

    const float ni = nrm[i];
#pragma unroll 4
    for (int j = 0; j < NN; ++j) {
        const float dot  = gb[i * NN + j];
        const float sim  = dot / (ni * nrm[j] + 1e-6f);
        const float wsym = 0.5f * (W[i * NN + j] + W[j * NN + i]);
        pp[i][j] = sim * wsym;
    }
    // re-zero own row for the next graph replay (thread i is the only reader of row i)
#pragma unroll
    for (int j = 0; j < NN; j += 4)
        *reinterpret_cast<float4*>(&gb[i * NN + j]) = make_float4(0.f, 0.f, 0.f, 0.f);

    e[i] = 0.0f;
    __syncthreads();

    const float li = lg[i];
    for (int it = 0; it < ITERS; ++it) {
        float acc = 0.0f;
#pragma unroll 8
        for (int j = 0; j < NN; ++j) {
            const float p = 1.0f / (1.0f + expf(-(li + e[j])));
            acc += (2.0f * p - 1.0f) * pp[i][j];
        }
        __syncthreads();
        e[i] = acc;
        __syncthreads();
    }

    red[i] = e[i];
    __syncthreads();
    for (int s = 32; s > 0; s >>= 1) {
        if (i < s) red[i] += red[i + s];
        __syncthreads();
    }
    const float meanE = red[0] * (1.0f / 64.0f);
    out[b * NN + i] = lg[i] + meanE;
}

extern "C" void kernel_launch(void* const* d_in, const int* in_sizes, int n_in,
                              void* d_out, int out_size) {
    const float* a_inter = (const float*)d_in[0];  // [8,64,64,32,32]
    const float* logits  = (const float*)d_in[1];  // [8,64]
    const float* W       = (const float*)d_in[2];  // [1,64,64]
    float* out           = (float*)d_out;          // [8,64]

    dim3 grid(SPLITS, BATCH);
    gram_mma_kernel<<<grid, 256>>>(a_inter);

    crf_kernel<<<BATCH, 64>>>(logits, W, out);
}

// round 7
// speedup vs baseline: 2.3282x; 2.2649x over previous
#include <cuda_runtime.h>
#include <cuda_fp16.h>
#include <cuda_bf16.h>
#include <math.h>
#include <stdint.h>

#define BATCH   8
#define NN      64
#define KTOT    65536
#define SPLITS  32
#define KCH     (KTOT / SPLITS)   // 2048
#define TILE_K  128               // floats per row per tile (512B bursts)
#define NTILES  (KCH / TILE_K)    // 16
#define HSTRIDE 136               // fp16 smem row stride
#define ITERS   10

// Gram scratch [B][N][N]; zero-initialized at module load, re-zeroed by crf_kernel
__device__ float g_gram[BATCH * NN * NN];

__device__ __forceinline__ uint32_t smem_u32(const void* p) {
    return (uint32_t)__cvta_generic_to_shared(p);
}

// ---------------------------------------------------------------------------
// Kernel 1: split-K Gram via fp16 mma.sync m16n8k16 + ldmatrix (unchanged R6).
// grid = (SPLITS, BATCH), block = 256 (8 warps: 4(M) x 2(N)).
// ---------------------------------------------------------------------------
__global__ void __launch_bounds__(256) gram_mma_kernel(const float* __restrict__ feats) {
    __shared__ __align__(16) __half hbuf[2][64 * HSTRIDE];

    const int tid  = threadIdx.x;
    const int wid  = tid >> 5;
    const int lane = tid & 31;
    const int tg   = lane & 3;
    const int wm   = wid >> 1;
    const int wn   = wid & 1;

    const int b = blockIdx.y;
    const int s = blockIdx.x;
    const float* base = feats + (size_t)b * NN * KTOT + (size_t)s * KCH;

    const int r0   = tid >> 5;
    const int coff = (tid & 31) * 4;

    const int a_row  = wm * 16 + (lane & 7) + ((lane >> 3) & 1) * 8;
    const int a_koff = (lane >> 4) * 8;
    const int b_col  = wn * 32 + (lane & 7) + ((lane >> 4) & 1) * 8;
    const int b_koff = ((lane >> 3) & 1) * 8;

    float c[4][4];
#pragma unroll
    for (int i = 0; i < 4; ++i)
#pragma unroll
        for (int j = 0; j < 4; ++j) c[i][j] = 0.0f;

#define STORE8(buf, row, off, v)                                                     \
    do {                                                                             \
        *reinterpret_cast<__half2*>(&hbuf[buf][(row) * HSTRIDE + (off)])     =       \
            __float22half2_rn(make_float2((v).x, (v).y));                            \
        *reinterpret_cast<__half2*>(&hbuf[buf][(row) * HSTRIDE + (off) + 2]) =       \
            __float22half2_rn(make_float2((v).z, (v).w));                            \
    } while (0)

    {
        float4 p[8];
#pragma unroll
        for (int i = 0; i < 8; ++i)
            p[i] = *reinterpret_cast<const float4*>(base + (size_t)(r0 + 8 * i) * KTOT + coff);
#pragma unroll
        for (int i = 0; i < 8; ++i)
            STORE8(0, r0 + 8 * i, coff, p[i]);
    }

    for (int t = 0; t < NTILES; ++t) {
        __syncthreads();

        float4 p[8];
        if (t + 1 < NTILES) {
            const float* nxt = base + (t + 1) * TILE_K;
#pragma unroll
            for (int i = 0; i < 8; ++i)
                p[i] = *reinterpret_cast<const float4*>(nxt + (size_t)(r0 + 8 * i) * KTOT + coff);
        }

        const __half* S = &hbuf[t & 1][0];
#pragma unroll
        for (int kk = 0; kk < 8; ++kk) {
            const int k0 = kk * 16;
            uint32_t a0, a1, a2, a3, b01[2], b23[2], b45[2], b67[2];
            {
                uint32_t addr = smem_u32(S + a_row * HSTRIDE + k0 + a_koff);
                asm volatile("ldmatrix.sync.aligned.m8n8.x4.shared.b16 {%0,%1,%2,%3}, [%4];"
                             : "=r"(a0), "=r"(a1), "=r"(a2), "=r"(a3) : "r"(addr));
            }
            {
                uint32_t addr = smem_u32(S + b_col * HSTRIDE + k0 + b_koff);
                asm volatile("ldmatrix.sync.aligned.m8n8.x4.shared.b16 {%0,%1,%2,%3}, [%4];"
                             : "=r"(b01[0]), "=r"(b01[1]), "=r"(b23[0]), "=r"(b23[1]) : "r"(addr));
            }
            {
                uint32_t addr = smem_u32(S + (b_col + 16) * HSTRIDE + k0 + b_koff);
                asm volatile("ldmatrix.sync.aligned.m8n8.x4.shared.b16 {%0,%1,%2,%3}, [%4];"
                             : "=r"(b45[0]), "=r"(b45[1]), "=r"(b67[0]), "=r"(b67[1]) : "r"(addr));
            }
#define MMA16(accv, bb)                                                         \
    asm volatile("mma.sync.aligned.m16n8k16.row.col.f32.f16.f16.f32 "          \
                 "{%0,%1,%2,%3}, {%4,%5,%6,%7}, {%8,%9}, {%0,%1,%2,%3};"       \
                 : "+f"(accv[0]), "+f"(accv[1]), "+f"(accv[2]), "+f"(accv[3])  \
                 : "r"(a0), "r"(a1), "r"(a2), "r"(a3), "r"(bb[0]), "r"(bb[1]))
            MMA16(c[0], b01);
            MMA16(c[1], b23);
            MMA16(c[2], b45);
            MMA16(c[3], b67);
#undef MMA16
        }

        if (t + 1 < NTILES) {
            const int nbuf = (t + 1) & 1;
#pragma unroll
            for (int i = 0; i < 8; ++i)
                STORE8(nbuf, r0 + 8 * i, coff, p[i]);
        }
    }
#undef STORE8

    float* gb = g_gram + (size_t)b * NN * NN;
    const int re = wm * 16 + (lane >> 2);
#pragma unroll
    for (int nt = 0; nt < 4; ++nt) {
        const int col = wn * 32 + nt * 8 + tg * 2;
        atomicAdd(&gb[(re)     * NN + col    ], c[nt][0]);
        atomicAdd(&gb[(re)     * NN + col + 1], c[nt][1]);
        atomicAdd(&gb[(re + 8) * NN + col    ], c[nt][2]);
        atomicAdd(&gb[(re + 8) * NN + col + 1], c[nt][3]);
    }
}

// ---------------------------------------------------------------------------
// Kernel 2 (REBUILT): CRF iterations + output. grid = BATCH, block = 256.
// Thread (i = t>>2, q = t&3) owns j in [16q, 16q+16); pp chunk in registers.
// 2*sigmoid(x)-1 = (1 - e^-x)/(1 + e^-x), e^-x via ex2.approx, rcp.approx.
// Double-buffered e[] -> one __syncthreads per iteration.
// Also re-zeroes g_gram for the next graph replay.
// ---------------------------------------------------------------------------
__global__ void __launch_bounds__(256) crf_kernel(const float* __restrict__ logits,
                                                  const float* __restrict__ W,
                                                  float* __restrict__ out) {
    const int b   = blockIdx.x;
    const int tid = threadIdx.x;
    const int i   = tid >> 2;     // row 0..63
    const int q   = tid & 3;      // j-quarter
    const int j0  = q * 16;

    __shared__ float nrm[64];
    __shared__ float lg[64];
    __shared__ float ebuf[2][64];
    __shared__ float red[64];

    float* gb = g_gram + (size_t)b * NN * NN;

    if (tid < 64) {
        nrm[tid] = sqrtf(gb[tid * NN + tid]);
        lg[tid]  = logits[b * NN + tid];
        ebuf[0][tid] = 0.0f;
    }
    __syncthreads();

    // pp chunk -> registers; then re-zero the gram cols we consumed
    const float ni = nrm[i];
    float pp[16];
#pragma unroll
    for (int jj = 0; jj < 16; ++jj) {
        const int j = j0 + jj;
        const float dot  = gb[i * NN + j];
        const float sim  = dot / (ni * nrm[j] + 1e-6f);
        const float wsym = 0.5f * (W[i * NN + j] + W[j * NN + i]);
        pp[jj] = sim * wsym;
    }
#pragma unroll
    for (int jj = 0; jj < 16; jj += 4)
        *reinterpret_cast<float4*>(&gb[i * NN + j0 + jj]) = make_float4(0.f, 0.f, 0.f, 0.f);

    const float li = lg[i];
    int cur = 0;
    for (int it = 0; it < ITERS; ++it) {
        float acc = 0.0f;
        const float* e = ebuf[cur];
#pragma unroll
        for (int jj = 0; jj < 16; ++jj) {
            const float x = li + e[j0 + jj];
            float t, r;
            asm("ex2.approx.f32 %0, %1;" : "=f"(t) : "f"(x * -1.4426950408889634f)); // e^-x
            asm("rcp.approx.f32 %0, %1;" : "=f"(r) : "f"(1.0f + t));
            acc = fmaf((1.0f - t) * r, pp[jj], acc);   // tanh(x/2) * pp
        }
        // reduce across the 4 lanes owning row i (lanes differ only in q)
        acc += __shfl_xor_sync(0xFFFFFFFF, acc, 1);
        acc += __shfl_xor_sync(0xFFFFFFFF, acc, 2);
        if (q == 0) ebuf[cur ^ 1][i] = acc;
        __syncthreads();
        cur ^= 1;
    }

    // mean over final e, then output
    if (tid < 64) red[tid] = ebuf[cur][tid];
    __syncthreads();
    if (tid < 32) red[tid] += red[tid + 32];
    __syncthreads();
    if (tid < 64) {
        float v = (tid < 32) ? red[tid] : 0.0f;
        // warp 0..1: only warp 0 lanes hold partials; finish with shuffles in warp 0
    }
    if (tid < 32) {
        float v = red[tid];
        v += __shfl_xor_sync(0xFFFFFFFF, v, 16);
        v += __shfl_xor_sync(0xFFFFFFFF, v, 8);
        v += __shfl_xor_sync(0xFFFFFFFF, v, 4);
        v += __shfl_xor_sync(0xFFFFFFFF, v, 2);
        v += __shfl_xor_sync(0xFFFFFFFF, v, 1);
        if (tid == 0) red[0] = v;
    }
    __syncthreads();
    if (tid < 64) {
        const float meanE = red[0] * (1.0f / 64.0f);
        out[b * NN + tid] = lg[tid] + meanE;
    }
}

extern "C" void kernel_launch(void* const* d_in, const int* in_sizes, int n_in,
                              void* d_out, int out_size) {
    const float* a_inter = (const float*)d_in[0];  // [8,64,64,32,32]
    const float* logits  = (const float*)d_in[1];  // [8,64]
    const float* W       = (const float*)d_in[2];  // [1,64,64]
    float* out           = (float*)d_out;          // [8,64]

    dim3 grid(SPLITS, BATCH);
    gram_mma_kernel<<<grid, 256>>>(a_inter);

    crf_kernel<<<BATCH, 256>>>(logits, W, out);
}